// round 6
// baseline (speedup 1.0000x reference)
#include <cuda_runtime.h>

#define Nn 128
#define Ff 16
#define FP 32
#define NM1 127

__global__ void __launch_bounds__(256) gat_one(
    const float* __restrict__ x,
    const float* __restrict__ w,
    const float* __restrict__ a,
    float*       __restrict__ out,
    int NR)
{
    __shared__ float v1[Ff], v2[Ff];
    __shared__ float s1[Nn], s2[Nn + 1];    // pad so s2[k+1] in-bounds for k=127
    const int tid = threadIdx.x;
    const int b   = blockIdx.y;

    // --- threads 0..127: x prefetch LDGs issued first, latency overlapped ---
    float xr[Ff];
    if (tid < Nn) {
        const float* xb = x + (size_t)b * Ff * Nn + tid;
        #pragma unroll
        for (int f = 0; f < Ff; ++f)
            xr[f] = xb[f * Nn];
    }

    // --- warp 4 computes v1/v2 = w^T a1 / w^T a2 concurrently ---
    if (tid >= 128 && tid < 160) {
        const int t = tid - 128;
        const int f = t & (Ff - 1);
        const float* av = a + (t < Ff ? 0 : FP);
        float acc = 0.f;
        #pragma unroll
        for (int g = 0; g < FP; ++g)
            acc += w[g * Ff + f] * av[g];
        if (t < Ff) v1[f] = acc; else v2[f] = acc;
    }
    if (tid == 160) s2[Nn] = 0.f;
    __syncthreads();

    // --- s1[n] = x[b,:,n].v1 ; s2[n] = x[b,:,n].v2 ---
    if (tid < Nn) {
        float acc1 = 0.f, acc2 = 0.f;
        #pragma unroll
        for (int f = 0; f < Ff; ++f) {
            acc1 += xr[f] * v1[f];
            acc2 += xr[f] * v2[f];
        }
        s1[tid] = acc1;
        s2[tid] = acc2;
    }
    __syncthreads();

    // --- hot loop: block writes 16 rows [r0, r0+16) of batch b ---
    // thread = fixed column k; its two possible s2 values live in registers
    const int k  = tid & (Nn - 1);
    const int rg = tid >> 7;                 // 0 or 1
    const int r0 = blockIdx.x * 16;

    const float s2a = s2[k];                 // used when k < r
    const float s2b = s2[k + 1];             // used when k >= r

    float* ob = out + (size_t)b * NR;

    if (k < NM1) {
        #pragma unroll
        for (int i = 0; i < 16; i += 2) {
            const int r = r0 + i + rg;
            const float s1v = s1[r];                       // warp-broadcast LDS
            ob[r * NM1 + k] = s1v + (k >= r ? s2b : s2a);  // FSEL + FADD + STG
        }
    }
}

extern "C" void kernel_launch(void* const* d_in, const int* in_sizes, int n_in,
                              void* d_out, int out_size) {
    const float* x = (const float*)d_in[0];
    const float* w = (const float*)d_in[1];
    const float* a = (const float*)d_in[2];
    float*     out = (float*)d_out;

    const int B  = in_sizes[0] / (Ff * Nn);   // x is (B, F, N)
    const int NR = in_sizes[3];               // N*(N-1) = 16256

    dim3 grid(Nn / 16, B);                    // (8, 64) = 512 blocks
    gat_one<<<grid, 256>>>(x, w, a, out, NR);
}